// round 3
// baseline (speedup 1.0000x reference)
#include <cuda_runtime.h>

typedef unsigned long long u64;

// ---------------------------------------------------------------------------
// Packed f32x2 helpers (FFMA2: ptxas never emits this from C++; PTX only)
// ---------------------------------------------------------------------------
__device__ __forceinline__ u64 fma2(u64 a, u64 b, u64 c) {
    u64 d;
    asm("fma.rn.f32x2 %0, %1, %2, %3;" : "=l"(d) : "l"(a), "l"(b), "l"(c));
    return d;
}
__device__ __forceinline__ u64 dup2(float v) {
    u64 r;
    asm("mov.b64 %0, {%1, %1};" : "=l"(r) : "f"(v));
    return r;
}
__device__ __forceinline__ void up2(u64 v, float& lo, float& hi) {
    asm("mov.b64 {%0, %1}, %2;" : "=f"(lo), "=f"(hi) : "l"(v));
}

// ---------------------------------------------------------------------------
// Scratch (allocation-free rule: __device__ globals)
// ---------------------------------------------------------------------------
static __device__ float g_Wm[64 * 64];
// y[bi][co][h][w], bi = b*64 + i : 512*16*62*62 floats (~126 MB)
static __device__ float g_y[512u * 16u * 62u * 62u];

// ---------------------------------------------------------------------------
// Kernel 1: 16->16 ch 3x3 VALID conv over 512 images of 64x64.
// grid.x = 512*8 strips (8 output rows each) + 1 block building g_Wm.
// 128 threads: thread = (cohalf{0,1}, hh[0,8), wg[0,8)) -> 8 co x 8 w tile,
// accumulators packed in co-pairs (f32x2). Weight LDS is warp-broadcast.
// ---------------------------------------------------------------------------
__global__ __launch_bounds__(128) void conv_kernel(const float* __restrict__ x,
                                                   const float* __restrict__ ker,
                                                   const float* __restrict__ c0p,
                                                   const float* __restrict__ c1p,
                                                   const float* __restrict__ c2p) {
    __shared__ __align__(16) float xs[16][10][68];    // 43520 B
    __shared__ __align__(16) float ks[16][3][3][16];  // [cin][kh][kw][co], 9216 B

    int tid = threadIdx.x;

    if (blockIdx.x == 512 * 8) {
        // ---- TT-matrix reconstruction (hidden under the conv wave) ----
        float* s0 = &xs[0][0][0];
        float* s1 = s0 + 128;
        float* s2 = s1 + 1024;
        for (int i = tid; i < 128; i += 128) s0[i] = c0p[i];
        for (int i = tid; i < 1024; i += 128) s1[i] = c1p[i];
        for (int i = tid; i < 128; i += 128) s2[i] = c2p[i];
        __syncthreads();
        for (int e = tid; e < 4096; e += 128) {
            int i = e >> 6, j = e & 63;
            int i1 = i >> 4, i2 = (i >> 2) & 3, i3 = i & 3;
            int j1 = j >> 4, j2 = (j >> 2) & 3, j3 = j & 3;
            float s = 0.f;
            #pragma unroll
            for (int r1 = 0; r1 < 8; ++r1) {
                float a = s0[(i1 * 4 + j1) * 8 + r1];
                float t = 0.f;
                #pragma unroll
                for (int r2 = 0; r2 < 8; ++r2)
                    t += s1[((r1 * 4 + i2) * 4 + j2) * 8 + r2] * s2[(r2 * 4 + i3) * 4 + j3];
                s = fmaf(a, t, s);
            }
            g_Wm[e] = s;
        }
        return;
    }

    int bi = blockIdx.x >> 3;
    int strip = blockIdx.x & 7;
    int r0 = strip * 8;

    // kernel: flat input [co][cin][kh][kw] -> smem [cin][kh][kw][co]
    for (int idx = tid; idx < 2304; idx += 128) {
        int co = idx / 144, rem = idx % 144;
        int cc = rem / 9, kk = rem % 9;
        ks[cc][kk / 3][kk % 3][co] = ker[idx];
    }
    // input rows r0 .. r0+9 (clamped), all 16 channels
    const float* xb = x + (size_t)bi * (16 * 64 * 64);
    for (int idx = tid; idx < 16 * 10 * 68; idx += 128) {
        int w = idx % 68;
        int rr = (idx / 68) % 10;
        int cc = idx / 680;
        int rg = r0 + rr; if (rg > 63) rg = 63;
        xs[cc][rr][w] = (w < 64) ? xb[(cc * 64 + rg) * 64 + w] : 0.f;
    }
    __syncthreads();

    int wg = tid & 7;
    int hh = (tid >> 3) & 7;
    int cohalf = tid >> 6;
    int w0 = wg * 8;
    int co0 = cohalf * 8;
    int h = r0 + hh;

    u64 acc2[4][8];  // [co-pair][w]
    #pragma unroll
    for (int cp = 0; cp < 4; ++cp)
        #pragma unroll
        for (int p = 0; p < 8; ++p) acc2[cp][p] = 0ull;

    #pragma unroll 1
    for (int cc = 0; cc < 16; ++cc) {
        #pragma unroll
        for (int kh = 0; kh < 3; ++kh) {
            // weights: warp-uniform address -> broadcast; co-pairs pre-packed
            u64 kr2[3][4];
            #pragma unroll
            for (int kw = 0; kw < 3; ++kw) {
                ulonglong2 a = *reinterpret_cast<const ulonglong2*>(&ks[cc][kh][kw][co0]);
                ulonglong2 b = *reinterpret_cast<const ulonglong2*>(&ks[cc][kh][kw][co0 + 4]);
                kr2[kw][0] = a.x; kr2[kw][1] = a.y;
                kr2[kw][2] = b.x; kr2[kw][3] = b.y;
            }
            const float* xrow = &xs[cc][hh + kh][w0];
            float4 xa = *reinterpret_cast<const float4*>(xrow);
            float4 xb4 = *reinterpret_cast<const float4*>(xrow + 4);
            float2 xc = *reinterpret_cast<const float2*>(xrow + 8);
            u64 xd[10] = {dup2(xa.x), dup2(xa.y), dup2(xa.z), dup2(xa.w),
                          dup2(xb4.x), dup2(xb4.y), dup2(xb4.z), dup2(xb4.w),
                          dup2(xc.x), dup2(xc.y)};
            #pragma unroll
            for (int kw = 0; kw < 3; ++kw)
                #pragma unroll
                for (int p = 0; p < 8; ++p) {
                    u64 xv = xd[p + kw];
                    #pragma unroll
                    for (int cp = 0; cp < 4; ++cp)
                        acc2[cp][p] = fma2(xv, kr2[kw][cp], acc2[cp][p]);
                }
        }
    }

    if (h < 62) {
        float* yb = g_y + (size_t)bi * (16 * 62 * 62);
        #pragma unroll
        for (int cp = 0; cp < 4; ++cp) {
            float lo[8], hi[8];
            #pragma unroll
            for (int p = 0; p < 8; ++p) up2(acc2[cp][p], lo[p], hi[p]);
            int coA = co0 + 2 * cp, coB = coA + 1;
            size_t baseA = ((size_t)coA * 62 + h) * 62 + w0;
            size_t baseB = ((size_t)coB * 62 + h) * 62 + w0;
            int nw = (w0 + 8 <= 62) ? 8 : (62 - w0);  // wg==7 -> 6
            // offsets are always even -> 8B-aligned float2 stores
            #pragma unroll
            for (int q = 0; q < 4; ++q) {
                if (2 * q < nw) {
                    *reinterpret_cast<float2*>(yb + baseA + 2 * q) = make_float2(lo[2 * q], lo[2 * q + 1]);
                    *reinterpret_cast<float2*>(yb + baseB + 2 * q) = make_float2(hi[2 * q], hi[2 * q + 1]);
                }
            }
        }
    }
}

// ---------------------------------------------------------------------------
// Kernel 2: out[b][co][p][j] = sum_i y[b*64+i][co][p] * Wm[i][j] + bias[j]
// grid = (31 pixel-chunks of 128, 16 co, 8 b); 256 threads = 8 warps.
// warp lane = (jq = lane&7, pq = lane>>3): thread tile 8 j x 4 p.
// Y float4 load is 8-way broadcast; W loads pre-packed j-pairs; stores
// coalesce into 256B runs along the j-innermost output dim.
// ---------------------------------------------------------------------------
__global__ __launch_bounds__(256) void mix_kernel(const float* __restrict__ bias,
                                                  float* __restrict__ out) {
    __shared__ __align__(16) float Ysm[64][128];  // 32768 B
    __shared__ __align__(16) float Wsm[64][64];   // 16384 B

    int p0 = blockIdx.x * 128;
    int co = blockIdx.y;
    int b  = blockIdx.z;
    int tid = threadIdx.x;

    for (int idx = tid; idx < 1024; idx += 256)
        reinterpret_cast<float4*>(&Wsm[0][0])[idx] =
            reinterpret_cast<const float4*>(g_Wm)[idx];

    for (int idx = tid; idx < 2048; idx += 256) {
        int i = idx >> 5;
        int q = idx & 31;
        int pp = p0 + q * 4;
        const float* src = &g_y[((size_t)((b * 64 + i) * 16 + co)) * 3844];
        float4 v;
        if (pp + 3 < 3844) {
            v = *reinterpret_cast<const float4*>(src + pp);
        } else {
            v.x = (pp + 0 < 3844) ? src[pp + 0] : 0.f;
            v.y = (pp + 1 < 3844) ? src[pp + 1] : 0.f;
            v.z = (pp + 2 < 3844) ? src[pp + 2] : 0.f;
            v.w = (pp + 3 < 3844) ? src[pp + 3] : 0.f;
        }
        *reinterpret_cast<float4*>(&Ysm[i][q * 4]) = v;
    }
    __syncthreads();

    int lane = tid & 31;
    int warp = tid >> 5;
    int jq = lane & 7;
    int pq = lane >> 3;
    int j0 = jq * 8;
    int pbase = warp * 16 + pq * 4;

    u64 acc2[4][4];  // [j-pair][p]
    #pragma unroll
    for (int jp = 0; jp < 4; ++jp)
        #pragma unroll
        for (int p = 0; p < 4; ++p) acc2[jp][p] = 0ull;

    #pragma unroll 4
    for (int k = 0; k < 64; ++k) {
        ulonglong2 wa = *reinterpret_cast<const ulonglong2*>(&Wsm[k][j0]);
        ulonglong2 wb = *reinterpret_cast<const ulonglong2*>(&Wsm[k][j0 + 4]);
        u64 wv[4] = {wa.x, wa.y, wb.x, wb.y};
        float4 yv = *reinterpret_cast<const float4*>(&Ysm[k][pbase]);
        u64 yd[4] = {dup2(yv.x), dup2(yv.y), dup2(yv.z), dup2(yv.w)};
        #pragma unroll
        for (int p = 0; p < 4; ++p)
            #pragma unroll
            for (int jp = 0; jp < 4; ++jp)
                acc2[jp][p] = fma2(yd[p], wv[jp], acc2[jp][p]);
    }

    float bv[8];
    #pragma unroll
    for (int j = 0; j < 8; ++j) bv[j] = bias[j0 + j];

    size_t rowbase = (size_t)(b * 16 + co) * 3844;
    #pragma unroll
    for (int p = 0; p < 4; ++p) {
        int pp = p0 + pbase + p;
        if (pp < 3844) {
            float f[8];
            #pragma unroll
            for (int jp = 0; jp < 4; ++jp) up2(acc2[jp][p], f[2 * jp], f[2 * jp + 1]);
            float* o = &out[(rowbase + pp) * 64 + j0];
            *reinterpret_cast<float4*>(o) =
                make_float4(f[0] + bv[0], f[1] + bv[1], f[2] + bv[2], f[3] + bv[3]);
            *reinterpret_cast<float4*>(o + 4) =
                make_float4(f[4] + bv[4], f[5] + bv[5], f[6] + bv[6], f[7] + bv[7]);
        }
    }
}

// ---------------------------------------------------------------------------
extern "C" void kernel_launch(void* const* d_in, const int* in_sizes, int n_in,
                              void* d_out, int out_size) {
    const float* x    = (const float*)d_in[0];
    const float* ker  = (const float*)d_in[1];
    const float* c0   = (const float*)d_in[2];
    const float* c1   = (const float*)d_in[3];
    const float* c2   = (const float*)d_in[4];
    const float* bias = (const float*)d_in[5];
    float* out = (float*)d_out;

    conv_kernel<<<512 * 8 + 1, 128>>>(x, ker, c0, c1, c2);
    mix_kernel<<<dim3(31, 16, 8), 256>>>(bias, out);
}

// round 4
// speedup vs baseline: 1.2374x; 1.2374x over previous
#include <cuda_runtime.h>

typedef unsigned long long u64;

// ---------------------------------------------------------------------------
// Packed f32x2 helpers (FFMA2: ptxas never emits this from C++; PTX only)
// ---------------------------------------------------------------------------
__device__ __forceinline__ u64 fma2(u64 a, u64 b, u64 c) {
    u64 d;
    asm("fma.rn.f32x2 %0, %1, %2, %3;" : "=l"(d) : "l"(a), "l"(b), "l"(c));
    return d;
}
__device__ __forceinline__ u64 dup2(float v) {
    u64 r;
    asm("mov.b64 %0, {%1, %1};" : "=l"(r) : "f"(v));
    return r;
}
__device__ __forceinline__ void up2(u64 v, float& lo, float& hi) {
    asm("mov.b64 {%0, %1}, %2;" : "=f"(lo), "=f"(hi) : "l"(v));
}

// ---------------------------------------------------------------------------
// Scratch (allocation-free rule: __device__ globals)
// ---------------------------------------------------------------------------
static __device__ float g_Wm[64 * 64];
// y[bi][co][h][w], bi = b*64 + i : 512*16*62*62 floats (~126 MB)
static __device__ float g_y[512u * 16u * 62u * 62u];

// ---------------------------------------------------------------------------
// Kernel 1: 16->16 ch 3x3 VALID conv over 512 images of 64x64.
// grid.x = 512*9 strips (7 output rows) + 1 block building g_Wm.
// 224 threads = 8 wg x 4 coq x 7 hh; a warp holds ONE row (warp id == hh).
// Thread tile: 4 co x 8 w, acc packed in co-pairs (f32x2).
// x stored as even/odd quad-split arrays -> all LDS are 16B-lane-stride
// contiguous (conflict-free) or warp-uniform (broadcast).
// ---------------------------------------------------------------------------
__global__ __launch_bounds__(224) void conv_kernel(const float* __restrict__ x,
                                                   const float* __restrict__ ker,
                                                   const float* __restrict__ c0p,
                                                   const float* __restrict__ c1p,
                                                   const float* __restrict__ c2p) {
    // XA[cc][r][t] = cols 8t..8t+3 (t=8 is zero pad), XB[cc][r][t] = cols 8t+4..8t+7
    __shared__ __align__(16) float4 XA[16][9][9];     // 20736 B
    __shared__ __align__(16) float4 XB[16][9][8];     // 18432 B
    __shared__ __align__(16) float  ks[16][3][3][16]; //  9216 B  (total 48384)

    int tid = threadIdx.x;

    if (blockIdx.x == 512 * 9) {
        // ---- TT-matrix reconstruction (hidden under the conv wave) ----
        float* s0 = reinterpret_cast<float*>(&XA[0][0][0]);
        float* s1 = s0 + 128;
        float* s2 = s1 + 1024;
        for (int i = tid; i < 128; i += 224) s0[i] = c0p[i];
        for (int i = tid; i < 1024; i += 224) s1[i] = c1p[i];
        for (int i = tid; i < 128; i += 224) s2[i] = c2p[i];
        __syncthreads();
        for (int e = tid; e < 4096; e += 224) {
            int i = e >> 6, j = e & 63;
            int i1 = i >> 4, i2 = (i >> 2) & 3, i3 = i & 3;
            int j1 = j >> 4, j2 = (j >> 2) & 3, j3 = j & 3;
            float s = 0.f;
            #pragma unroll
            for (int r1 = 0; r1 < 8; ++r1) {
                float a = s0[(i1 * 4 + j1) * 8 + r1];
                float t = 0.f;
                #pragma unroll
                for (int r2 = 0; r2 < 8; ++r2)
                    t += s1[((r1 * 4 + i2) * 4 + j2) * 8 + r2] * s2[(r2 * 4 + i3) * 4 + j3];
                s = fmaf(a, t, s);
            }
            g_Wm[e] = s;
        }
        return;
    }

    int bi = blockIdx.x / 9;
    int strip = blockIdx.x % 9;
    int r0 = strip * 7;

    // kernel weights: flat input [co][cin][kh][kw] -> smem [cin][kh][kw][co]
    for (int idx = tid; idx < 2304; idx += 224) {
        int co = idx / 144, rem = idx % 144;
        int cc = rem / 9, kk = rem % 9;
        ks[cc][kk / 3][kk % 3][co] = ker[idx];
    }
    // input rows r0 .. r0+8 (clamped), 16 channels, as quad-split float4s
    const float4* xq = reinterpret_cast<const float4*>(x + (size_t)bi * (16 * 64 * 64));
    for (int idx = tid; idx < 16 * 9 * 16; idx += 224) {
        int g = idx & 15;
        int rr = (idx >> 4) % 9;
        int cc = idx / (16 * 9);
        int rg = r0 + rr; if (rg > 63) rg = 63;
        float4 v = xq[((cc << 6) + rg) * 16 + g];
        if (g & 1) XB[cc][rr][g >> 1] = v;
        else       XA[cc][rr][g >> 1] = v;
    }
    // zero pad column t=8 of XA
    for (int idx = tid; idx < 16 * 9; idx += 224)
        XA[idx / 9][idx % 9][8] = make_float4(0.f, 0.f, 0.f, 0.f);
    __syncthreads();

    int wg  = tid & 7;
    int coq = (tid >> 3) & 3;
    int hh  = tid >> 5;           // warp id == row
    int w0  = wg * 8;
    int co0 = coq * 4;
    int h   = r0 + hh;

    u64 acc2[2][8];  // [co-pair][w]
    #pragma unroll
    for (int cp = 0; cp < 2; ++cp)
        #pragma unroll
        for (int p = 0; p < 8; ++p) acc2[cp][p] = 0ull;

    #pragma unroll 1
    for (int cc = 0; cc < 16; ++cc) {
        #pragma unroll
        for (int kh = 0; kh < 3; ++kh) {
            int r = hh + kh;
            float4 xa = XA[cc][r][wg];
            float4 xb = XB[cc][r][wg];
            float2 xc = *reinterpret_cast<const float2*>(&XA[cc][r][wg + 1]);
            u64 xd[10] = {dup2(xa.x), dup2(xa.y), dup2(xa.z), dup2(xa.w),
                          dup2(xb.x), dup2(xb.y), dup2(xb.z), dup2(xb.w),
                          dup2(xc.x), dup2(xc.y)};
            #pragma unroll
            for (int kw = 0; kw < 3; ++kw) {
                // 4 co weights = 2 packed pairs, warp-uniform -> broadcast
                ulonglong2 kv = *reinterpret_cast<const ulonglong2*>(&ks[cc][kh][kw][co0]);
                #pragma unroll
                for (int p = 0; p < 8; ++p) {
                    u64 xv = xd[p + kw];
                    acc2[0][p] = fma2(xv, kv.x, acc2[0][p]);
                    acc2[1][p] = fma2(xv, kv.y, acc2[1][p]);
                }
            }
        }
    }

    if (h < 62) {
        float* yb = g_y + (size_t)bi * (16 * 62 * 62);
        int nw = (w0 + 8 <= 62) ? 8 : (62 - w0);  // wg==7 -> 6
        #pragma unroll
        for (int cp = 0; cp < 2; ++cp) {
            float lo[8], hi[8];
            #pragma unroll
            for (int p = 0; p < 8; ++p) up2(acc2[cp][p], lo[p], hi[p]);
            int coA = co0 + 2 * cp, coB = coA + 1;
            size_t baseA = ((size_t)coA * 62 + h) * 62 + w0;
            size_t baseB = ((size_t)coB * 62 + h) * 62 + w0;
            #pragma unroll
            for (int q = 0; q < 4; ++q) {
                if (2 * q < nw) {
                    *reinterpret_cast<float2*>(yb + baseA + 2 * q) = make_float2(lo[2 * q], lo[2 * q + 1]);
                    *reinterpret_cast<float2*>(yb + baseB + 2 * q) = make_float2(hi[2 * q], hi[2 * q + 1]);
                }
            }
        }
    }
}

// ---------------------------------------------------------------------------
// Kernel 2: out[b][co][p][j] = sum_i y[b*64+i][co][p] * Wm[i][j] + bias[j]
// grid = (31 px-chunks of 128, 16 co, 8 b); 256 threads = 8 warps.
// lane = (jq = lane&7, pq = lane>>3): thread tile 8 j x 4 p.
// W split into even/odd quad arrays -> 16B lane stride (conflict-free,
// 4x dedup); Y one quad per thread (4 consecutive addrs/warp).
// ---------------------------------------------------------------------------
__global__ __launch_bounds__(256) void mix_kernel(const float* __restrict__ bias,
                                                  float* __restrict__ out) {
    __shared__ __align__(16) float4 WA[64][8];   //  8192 B  (quads j0..j0+3)
    __shared__ __align__(16) float4 WB[64][8];   //  8192 B  (quads j0+4..j0+7)
    __shared__ __align__(16) float4 Y4[64][32];  // 32768 B  (total 49152)

    int p0 = blockIdx.x * 128;
    int co = blockIdx.y;
    int b  = blockIdx.z;
    int tid = threadIdx.x;

    for (int idx = tid; idx < 1024; idx += 256) {
        int g = idx & 15;
        float4 v = reinterpret_cast<const float4*>(g_Wm)[idx];
        if (g & 1) WB[idx >> 4][g >> 1] = v;
        else       WA[idx >> 4][g >> 1] = v;
    }
    for (int idx = tid; idx < 2048; idx += 256) {
        int t = idx & 31;
        int i = idx >> 5;
        int pp = p0 + t * 4;
        const float* src = g_y + ((size_t)((b * 64 + i) * 16 + co)) * 3844;
        float4 v;
        if (pp + 3 < 3844) {
            v = *reinterpret_cast<const float4*>(src + pp);
        } else {
            v.x = (pp + 0 < 3844) ? src[pp + 0] : 0.f;
            v.y = (pp + 1 < 3844) ? src[pp + 1] : 0.f;
            v.z = (pp + 2 < 3844) ? src[pp + 2] : 0.f;
            v.w = (pp + 3 < 3844) ? src[pp + 3] : 0.f;
        }
        Y4[i][t] = v;
    }
    __syncthreads();

    int lane = tid & 31;
    int warp = tid >> 5;
    int jq = lane & 7;
    int pq = lane >> 3;
    int j0 = jq * 8;
    int pqg = warp * 4 + pq;      // quad index in [0,32)

    u64 acc2[4][4];  // [j-pair][p]
    #pragma unroll
    for (int jp = 0; jp < 4; ++jp)
        #pragma unroll
        for (int p = 0; p < 4; ++p) acc2[jp][p] = 0ull;

    #pragma unroll 4
    for (int k = 0; k < 64; ++k) {
        ulonglong2 wa = *reinterpret_cast<const ulonglong2*>(&WA[k][jq]);
        ulonglong2 wb = *reinterpret_cast<const ulonglong2*>(&WB[k][jq]);
        float4 yv = Y4[k][pqg];
        u64 yd[4] = {dup2(yv.x), dup2(yv.y), dup2(yv.z), dup2(yv.w)};
        #pragma unroll
        for (int p = 0; p < 4; ++p) {
            acc2[0][p] = fma2(yd[p], wa.x, acc2[0][p]);
            acc2[1][p] = fma2(yd[p], wa.y, acc2[1][p]);
            acc2[2][p] = fma2(yd[p], wb.x, acc2[2][p]);
            acc2[3][p] = fma2(yd[p], wb.y, acc2[3][p]);
        }
    }

    float bv[8];
    #pragma unroll
    for (int j = 0; j < 8; ++j) bv[j] = bias[j0 + j];

    size_t rowbase = (size_t)(b * 16 + co) * 3844;
    #pragma unroll
    for (int p = 0; p < 4; ++p) {
        int pp = p0 + pqg * 4 + p;
        if (pp < 3844) {
            float f[8];
            #pragma unroll
            for (int jp = 0; jp < 4; ++jp) up2(acc2[jp][p], f[2 * jp], f[2 * jp + 1]);
            float* o = &out[(rowbase + pp) * 64 + j0];
            *reinterpret_cast<float4*>(o) =
                make_float4(f[0] + bv[0], f[1] + bv[1], f[2] + bv[2], f[3] + bv[3]);
            *reinterpret_cast<float4*>(o + 4) =
                make_float4(f[4] + bv[4], f[5] + bv[5], f[6] + bv[6], f[7] + bv[7]);
        }
    }
}

// ---------------------------------------------------------------------------
extern "C" void kernel_launch(void* const* d_in, const int* in_sizes, int n_in,
                              void* d_out, int out_size) {
    const float* x    = (const float*)d_in[0];
    const float* ker  = (const float*)d_in[1];
    const float* c0   = (const float*)d_in[2];
    const float* c1   = (const float*)d_in[3];
    const float* c2   = (const float*)d_in[4];
    const float* bias = (const float*)d_in[5];
    float* out = (float*)d_out;

    conv_kernel<<<512 * 9 + 1, 224>>>(x, ker, c0, c1, c2);
    mix_kernel<<<dim3(31, 16, 8), 256>>>(bias, out);
}

// round 6
// speedup vs baseline: 1.3438x; 1.0860x over previous
#include <cuda_runtime.h>
#include <cuda_bf16.h>
#include <cstdint>

typedef unsigned long long u64;

// ---------------------------------------------------------------------------
// Packed f32x2 helpers (conv path)
// ---------------------------------------------------------------------------
__device__ __forceinline__ u64 fma2(u64 a, u64 b, u64 c) {
    u64 d;
    asm("fma.rn.f32x2 %0, %1, %2, %3;" : "=l"(d) : "l"(a), "l"(b), "l"(c));
    return d;
}
__device__ __forceinline__ u64 dup2(float v) {
    u64 r;
    asm("mov.b64 %0, {%1, %1};" : "=l"(r) : "f"(v));
    return r;
}
__device__ __forceinline__ void up2(u64 v, float& lo, float& hi) {
    asm("mov.b64 {%0, %1}, %2;" : "=f"(lo), "=f"(hi) : "l"(v));
}

// ---------------------------------------------------------------------------
// Tensor-core helpers (baseline PTX only: ldmatrix sm_75+, mma.sync sm_80+)
// ---------------------------------------------------------------------------
__device__ __forceinline__ uint32_t smem_u32(const void* p) {
    uint32_t a;
    asm("{ .reg .u64 t; cvta.to.shared.u64 t, %1; cvt.u32.u64 %0, t; }" : "=r"(a) : "l"(p));
    return a;
}

#define LDSM_X4(r0, r1, r2, r3, a) \
    asm volatile("ldmatrix.sync.aligned.m8n8.x4.shared.b16 {%0,%1,%2,%3}, [%4];" \
        : "=r"(r0), "=r"(r1), "=r"(r2), "=r"(r3) : "r"(a))
#define LDSM_X4T(r0, r1, r2, r3, a) \
    asm volatile("ldmatrix.sync.aligned.m8n8.x4.trans.shared.b16 {%0,%1,%2,%3}, [%4];" \
        : "=r"(r0), "=r"(r1), "=r"(r2), "=r"(r3) : "r"(a))

__device__ __forceinline__ void mma16816(float* d, const uint32_t* a,
                                         uint32_t b0, uint32_t b1) {
    asm volatile(
        "mma.sync.aligned.m16n8k16.row.col.f32.bf16.bf16.f32 "
        "{%0,%1,%2,%3}, {%4,%5,%6,%7}, {%8,%9}, {%0,%1,%2,%3};"
        : "+f"(d[0]), "+f"(d[1]), "+f"(d[2]), "+f"(d[3])
        : "r"(a[0]), "r"(a[1]), "r"(a[2]), "r"(a[3]), "r"(b0), "r"(b1));
}

__device__ __forceinline__ uint32_t bsplit_pack_hi(float v0, float v1, uint32_t& lo) {
    __nv_bfloat16 h0 = __float2bfloat16_rn(v0);
    __nv_bfloat16 h1 = __float2bfloat16_rn(v1);
    __nv_bfloat16 l0 = __float2bfloat16_rn(v0 - __bfloat162float(h0));
    __nv_bfloat16 l1 = __float2bfloat16_rn(v1 - __bfloat162float(h1));
    lo = (uint32_t)__bfloat16_as_ushort(l0) | ((uint32_t)__bfloat16_as_ushort(l1) << 16);
    return (uint32_t)__bfloat16_as_ushort(h0) | ((uint32_t)__bfloat16_as_ushort(h1) << 16);
}

#define STS128(a, r0, r1, r2, r3) \
    asm volatile("st.shared.v4.b32 [%0], {%1,%2,%3,%4};" :: "r"(a), "r"(r0), "r"(r1), "r"(r2), "r"(r3) : "memory")

// ---------------------------------------------------------------------------
// Scratch
// ---------------------------------------------------------------------------
static __device__ float g_Wm[64 * 64];
static __device__ float g_y[512u * 16u * 62u * 62u];

// ---------------------------------------------------------------------------
// Kernel 1: conv (UNCHANGED from R4) + hidden Wm build in extra block
// ---------------------------------------------------------------------------
__global__ __launch_bounds__(224) void conv_kernel(const float* __restrict__ x,
                                                   const float* __restrict__ ker,
                                                   const float* __restrict__ c0p,
                                                   const float* __restrict__ c1p,
                                                   const float* __restrict__ c2p) {
    __shared__ __align__(16) float4 XA[16][9][9];
    __shared__ __align__(16) float4 XB[16][9][8];
    __shared__ __align__(16) float  ks[16][3][3][16];

    int tid = threadIdx.x;

    if (blockIdx.x == 512 * 9) {
        float* s0 = reinterpret_cast<float*>(&XA[0][0][0]);
        float* s1 = s0 + 128;
        float* s2 = s1 + 1024;
        for (int i = tid; i < 128; i += 224) s0[i] = c0p[i];
        for (int i = tid; i < 1024; i += 224) s1[i] = c1p[i];
        for (int i = tid; i < 128; i += 224) s2[i] = c2p[i];
        __syncthreads();
        for (int e = tid; e < 4096; e += 224) {
            int i = e >> 6, j = e & 63;
            int i1 = i >> 4, i2 = (i >> 2) & 3, i3 = i & 3;
            int j1 = j >> 4, j2 = (j >> 2) & 3, j3 = j & 3;
            float s = 0.f;
            #pragma unroll
            for (int r1 = 0; r1 < 8; ++r1) {
                float a = s0[(i1 * 4 + j1) * 8 + r1];
                float t = 0.f;
                #pragma unroll
                for (int r2 = 0; r2 < 8; ++r2)
                    t += s1[((r1 * 4 + i2) * 4 + j2) * 8 + r2] * s2[(r2 * 4 + i3) * 4 + j3];
                s = fmaf(a, t, s);
            }
            g_Wm[e] = s;
        }
        return;
    }

    int bi = blockIdx.x / 9;
    int strip = blockIdx.x % 9;
    int r0 = strip * 7;

    for (int idx = tid; idx < 2304; idx += 224) {
        int co = idx / 144, rem = idx % 144;
        int cc = rem / 9, kk = rem % 9;
        ks[cc][kk / 3][kk % 3][co] = ker[idx];
    }
    const float4* xq = reinterpret_cast<const float4*>(x + (size_t)bi * (16 * 64 * 64));
    for (int idx = tid; idx < 16 * 9 * 16; idx += 224) {
        int g = idx & 15;
        int rr = (idx >> 4) % 9;
        int cc = idx / (16 * 9);
        int rg = r0 + rr; if (rg > 63) rg = 63;
        float4 v = xq[((cc << 6) + rg) * 16 + g];
        if (g & 1) XB[cc][rr][g >> 1] = v;
        else       XA[cc][rr][g >> 1] = v;
    }
    for (int idx = tid; idx < 16 * 9; idx += 224)
        XA[idx / 9][idx % 9][8] = make_float4(0.f, 0.f, 0.f, 0.f);
    __syncthreads();

    int wg  = tid & 7;
    int coq = (tid >> 3) & 3;
    int hh  = tid >> 5;
    int w0  = wg * 8;
    int co0 = coq * 4;
    int h   = r0 + hh;

    u64 acc2[2][8];
    #pragma unroll
    for (int cp = 0; cp < 2; ++cp)
        #pragma unroll
        for (int p = 0; p < 8; ++p) acc2[cp][p] = 0ull;

    #pragma unroll 1
    for (int cc = 0; cc < 16; ++cc) {
        #pragma unroll
        for (int kh = 0; kh < 3; ++kh) {
            int r = hh + kh;
            float4 xa = XA[cc][r][wg];
            float4 xb = XB[cc][r][wg];
            float2 xc = *reinterpret_cast<const float2*>(&XA[cc][r][wg + 1]);
            u64 xd[10] = {dup2(xa.x), dup2(xa.y), dup2(xa.z), dup2(xa.w),
                          dup2(xb.x), dup2(xb.y), dup2(xb.z), dup2(xb.w),
                          dup2(xc.x), dup2(xc.y)};
            #pragma unroll
            for (int kw = 0; kw < 3; ++kw) {
                ulonglong2 kv = *reinterpret_cast<const ulonglong2*>(&ks[cc][kh][kw][co0]);
                #pragma unroll
                for (int p = 0; p < 8; ++p) {
                    u64 xv = xd[p + kw];
                    acc2[0][p] = fma2(xv, kv.x, acc2[0][p]);
                    acc2[1][p] = fma2(xv, kv.y, acc2[1][p]);
                }
            }
        }
    }

    if (h < 62) {
        float* yb = g_y + (size_t)bi * (16 * 62 * 62);
        int nw = (w0 + 8 <= 62) ? 8 : (62 - w0);
        #pragma unroll
        for (int cp = 0; cp < 2; ++cp) {
            float lo[8], hi[8];
            #pragma unroll
            for (int p = 0; p < 8; ++p) up2(acc2[cp][p], lo[p], hi[p]);
            int coA = co0 + 2 * cp, coB = coA + 1;
            size_t baseA = ((size_t)coA * 62 + h) * 62 + w0;
            size_t baseB = ((size_t)coB * 62 + h) * 62 + w0;
            #pragma unroll
            for (int q = 0; q < 4; ++q) {
                if (2 * q < nw) {
                    *reinterpret_cast<float2*>(yb + baseA + 2 * q) = make_float2(lo[2 * q], lo[2 * q + 1]);
                    *reinterpret_cast<float2*>(yb + baseB + 2 * q) = make_float2(hi[2 * q], hi[2 * q + 1]);
                }
            }
        }
    }
}

// ---------------------------------------------------------------------------
// Kernel 2: mix via mma.sync bf16 split (D = Ahi*Bhi + Ahi*Blo + Alo*Bhi).
// Block = 128 pixels x 64 j; grid (31, 16 co, 8 b); 256 threads = 8 warps.
// A = y^T [p][i] hi/lo (pitch 144B: ldmatrix conflict-free), B = Wm [i][j]
// hi/lo row-major (ldmatrix.x4.trans for col-layout fragment).
// ---------------------------------------------------------------------------
static constexpr int PITCH = 144;                       // 72 bf16
static constexpr int SM_AHI  = 0;                       // 128*144 = 18432
static constexpr int SM_ALO  = 18432;                   // 18432
static constexpr int SM_BHI  = 36864;                   // 64*144 = 9216
static constexpr int SM_BLO  = 46080;                   // 9216
static constexpr int SM_BIAS = 55296;                   // 256
static constexpr int SM_MIX  = 55552;

__global__ __launch_bounds__(256) void mix_mma_kernel(const float* __restrict__ bias,
                                                      float* __restrict__ out) {
    extern __shared__ __align__(16) char smem[];
    uint32_t sb = smem_u32(smem);
    int tid = threadIdx.x;
    int lane = tid & 31;
    int warp = tid >> 5;
    int co = blockIdx.y;
    int b  = blockIdx.z;
    int p_base = blockIdx.x * 128;

    // ---- B = Wm hi/lo [i][j], row-major, pitch 144B ----
    if (tid < 128) {
        int i = tid & 63;
        int jh = tid >> 6;          // j-half: 32 j
        int j0 = jh * 32;
        const float4* src = reinterpret_cast<const float4*>(&g_Wm[i * 64 + j0]);
        uint32_t base = sb + i * PITCH + j0 * 2;
        #pragma unroll
        for (int q = 0; q < 4; ++q) {
            float4 v0 = src[2 * q];
            float4 v1 = src[2 * q + 1];
            uint32_t l0, l1, l2, l3;
            uint32_t h0 = bsplit_pack_hi(v0.x, v0.y, l0);
            uint32_t h1 = bsplit_pack_hi(v0.z, v0.w, l1);
            uint32_t h2 = bsplit_pack_hi(v1.x, v1.y, l2);
            uint32_t h3 = bsplit_pack_hi(v1.z, v1.w, l3);
            STS128(base + SM_BHI + q * 16, h0, h1, h2, h3);
            STS128(base + SM_BLO + q * 16, l0, l1, l2, l3);
        }
    }
    if (tid < 64)
        *reinterpret_cast<float*>(smem + SM_BIAS + tid * 4) = bias[tid];

    // ---- A = y^T [p][i] hi/lo ----
    {
        int p = tid & 127;
        int ih = tid >> 7;          // i-half: 32 i
        int i0 = ih * 32;
        int pg = p_base + p;
        bool pok = pg < 3844;
        const float* ybase = g_y + ((size_t)(b * 64 + i0) * 16 + co) * 3844 + pg;
        uint32_t base = sb + p * PITCH + i0 * 2;
        #pragma unroll
        for (int s = 0; s < 4; ++s) {
            float v[8];
            #pragma unroll
            for (int e = 0; e < 8; ++e)
                v[e] = pok ? ybase[(size_t)(s * 8 + e) * (16 * 3844)] : 0.f;
            uint32_t l0, l1, l2, l3;
            uint32_t h0 = bsplit_pack_hi(v[0], v[1], l0);
            uint32_t h1 = bsplit_pack_hi(v[2], v[3], l1);
            uint32_t h2 = bsplit_pack_hi(v[4], v[5], l2);
            uint32_t h3 = bsplit_pack_hi(v[6], v[7], l3);
            STS128(base + SM_AHI + s * 16, h0, h1, h2, h3);
            STS128(base + SM_ALO + s * 16, l0, l1, l2, l3);
        }
    }
    __syncthreads();

    // ---- mainloop: 4 k-steps of 16 ----
    float acc[8][4];
    #pragma unroll
    for (int nt = 0; nt < 8; ++nt)
        #pragma unroll
        for (int e = 0; e < 4; ++e) acc[nt][e] = 0.f;

    // A fragment address: row = warp*16 + (lane&15), k-col half = (lane>>4)*8
    uint32_t a_row = warp * 16 + (lane & 15);
    uint32_t a_off = sb + a_row * PITCH + (lane >> 4) * 16;
    // B fragment address: krow = (lane&15) within step, j = jp*16 + (lane>>4)*8
    uint32_t b_kr = (lane & 15);
    uint32_t b_jc = (lane >> 4) * 8;

    #pragma unroll
    for (int k = 0; k < 4; ++k) {
        uint32_t ahi[4], alo[4];
        LDSM_X4(ahi[0], ahi[1], ahi[2], ahi[3], a_off + SM_AHI + k * 32);
        LDSM_X4(alo[0], alo[1], alo[2], alo[3], a_off + SM_ALO + k * 32);

        #pragma unroll
        for (int jp = 0; jp < 4; ++jp) {
            uint32_t baddr = sb + (k * 16 + b_kr) * PITCH + (jp * 16 + b_jc) * 2;
            uint32_t bh[4], bl[4];
            LDSM_X4T(bh[0], bh[1], bh[2], bh[3], baddr + SM_BHI);
            LDSM_X4T(bl[0], bl[1], bl[2], bl[3], baddr + SM_BLO);
            mma16816(acc[2 * jp], ahi, bh[0], bh[1]);
            mma16816(acc[2 * jp], ahi, bl[0], bl[1]);
            mma16816(acc[2 * jp], alo, bh[0], bh[1]);
            mma16816(acc[2 * jp + 1], ahi, bh[2], bh[3]);
            mma16816(acc[2 * jp + 1], ahi, bl[2], bl[3]);
            mma16816(acc[2 * jp + 1], alo, bh[2], bh[3]);
        }
    }

    // ---- epilogue ----
    size_t rowbase = (size_t)(b * 16 + co) * 3844;
    int row0 = warp * 16 + (lane >> 2);
    int pm0 = p_base + row0;
    int pm1 = pm0 + 8;
    int jsub = (lane & 3) * 2;

    #pragma unroll
    for (int nt = 0; nt < 8; ++nt) {
        int j = nt * 8 + jsub;
        float2 bv = *reinterpret_cast<const float2*>(smem + SM_BIAS + j * 4);
        if (pm0 < 3844)
            *reinterpret_cast<float2*>(&out[(rowbase + pm0) * 64 + j]) =
                make_float2(acc[nt][0] + bv.x, acc[nt][1] + bv.y);
        if (pm1 < 3844)
            *reinterpret_cast<float2*>(&out[(rowbase + pm1) * 64 + j]) =
                make_float2(acc[nt][2] + bv.x, acc[nt][3] + bv.y);
    }
}

// ---------------------------------------------------------------------------
extern "C" void kernel_launch(void* const* d_in, const int* in_sizes, int n_in,
                              void* d_out, int out_size) {
    const float* x    = (const float*)d_in[0];
    const float* ker  = (const float*)d_in[1];
    const float* c0   = (const float*)d_in[2];
    const float* c1   = (const float*)d_in[3];
    const float* c2   = (const float*)d_in[4];
    const float* bias = (const float*)d_in[5];
    float* out = (float*)d_out;

    cudaFuncSetAttribute(mix_mma_kernel,
                         cudaFuncAttributeMaxDynamicSharedMemorySize, SM_MIX);

    conv_kernel<<<512 * 9 + 1, 224>>>(x, ker, c0, c1, c2);
    mix_mma_kernel<<<dim3(31, 16, 8), 256, SM_MIX>>>(bias, out);
}

// round 7
// speedup vs baseline: 1.6637x; 1.2381x over previous
#include <cuda_runtime.h>
#include <cuda_bf16.h>
#include <cstdint>

typedef unsigned long long u64;

// ---------------------------------------------------------------------------
// Tensor-core helpers (baseline PTX: ldmatrix sm_75+, mma.sync sm_80+)
// ---------------------------------------------------------------------------
__device__ __forceinline__ uint32_t smem_u32(const void* p) {
    uint32_t a;
    asm("{ .reg .u64 t; cvta.to.shared.u64 t, %1; cvt.u32.u64 %0, t; }" : "=r"(a) : "l"(p));
    return a;
}

#define LDSM_X4(r0, r1, r2, r3, a) \
    asm volatile("ldmatrix.sync.aligned.m8n8.x4.shared.b16 {%0,%1,%2,%3}, [%4];" \
        : "=r"(r0), "=r"(r1), "=r"(r2), "=r"(r3) : "r"(a))
#define LDSM_X4T(r0, r1, r2, r3, a) \
    asm volatile("ldmatrix.sync.aligned.m8n8.x4.trans.shared.b16 {%0,%1,%2,%3}, [%4];" \
        : "=r"(r0), "=r"(r1), "=r"(r2), "=r"(r3) : "r"(a))

__device__ __forceinline__ void mma16816(float* d, const uint32_t* a,
                                         uint32_t b0, uint32_t b1) {
    asm volatile(
        "mma.sync.aligned.m16n8k16.row.col.f32.bf16.bf16.f32 "
        "{%0,%1,%2,%3}, {%4,%5,%6,%7}, {%8,%9}, {%0,%1,%2,%3};"
        : "+f"(d[0]), "+f"(d[1]), "+f"(d[2]), "+f"(d[3])
        : "r"(a[0]), "r"(a[1]), "r"(a[2]), "r"(a[3]), "r"(b0), "r"(b1));
}

__device__ __forceinline__ void bsplit16(float v, unsigned short& h, unsigned short& l) {
    __nv_bfloat16 bh = __float2bfloat16_rn(v);
    __nv_bfloat16 bl = __float2bfloat16_rn(v - __bfloat162float(bh));
    h = __bfloat16_as_ushort(bh);
    l = __bfloat16_as_ushort(bl);
}

__device__ __forceinline__ uint32_t bsplit_pack_hi(float v0, float v1, uint32_t& lo) {
    __nv_bfloat16 h0 = __float2bfloat16_rn(v0);
    __nv_bfloat16 h1 = __float2bfloat16_rn(v1);
    __nv_bfloat16 l0 = __float2bfloat16_rn(v0 - __bfloat162float(h0));
    __nv_bfloat16 l1 = __float2bfloat16_rn(v1 - __bfloat162float(h1));
    lo = (uint32_t)__bfloat16_as_ushort(l0) | ((uint32_t)__bfloat16_as_ushort(l1) << 16);
    return (uint32_t)__bfloat16_as_ushort(h0) | ((uint32_t)__bfloat16_as_ushort(h1) << 16);
}

#define STS128(a, r0, r1, r2, r3) \
    asm volatile("st.shared.v4.b32 [%0], {%1,%2,%3,%4};" :: "r"(a), "r"(r0), "r"(r1), "r"(r2), "r"(r3) : "memory")

// swizzle: flip the 16B slot when bit7 set -> 8 consecutive w pixels (32B
// stride) occupy 8 distinct 16B slots => ldmatrix conflict-free.
#define SWZ(a) ((a) ^ (((a) >> 3) & 0x10))

// ---------------------------------------------------------------------------
// Scratch
// ---------------------------------------------------------------------------
static __device__ float g_Wm[64 * 64];
static __device__ float g_y[512u * 16u * 62u * 62u];

// ---------------------------------------------------------------------------
// Kernel 1: tensor-core conv. grid = 512 images x 8 row-strips (+1 Wm block).
// 256 thr = 8 warps; warp = one output row; 4 m16 w-tiles x n16 co.
// A = x [row 10][w 68][cin 16] bf16 hi/lo (swizzled); B = ker [tap][cin][co].
// 9 shifted-tap GEMMs, K=16 each, bf16 split (hh + hl + lh).
// ---------------------------------------------------------------------------
static constexpr int A_HI = 0;          // 10 * 2176 = 21760
static constexpr int A_LO = 21760;      // 21760
static constexpr int B_SM = 43520;      // 9 * 512 * 2 = 9216
static constexpr int SM_CONV = 52736;

__global__ __launch_bounds__(256) void conv_tc_kernel(const float* __restrict__ x,
                                                      const float* __restrict__ ker,
                                                      const float* __restrict__ c0p,
                                                      const float* __restrict__ c1p,
                                                      const float* __restrict__ c2p) {
    extern __shared__ __align__(128) char smem[];
    uint32_t sb = smem_u32(smem);
    int tid = threadIdx.x;

    if (blockIdx.x == 4096) {
        // ---- TT-matrix reconstruction (hidden under the conv wave) ----
        float* s0 = reinterpret_cast<float*>(smem);
        float* s1 = s0 + 128;
        float* s2 = s1 + 1024;
        for (int i = tid; i < 128; i += 256) s0[i] = c0p[i];
        for (int i = tid; i < 1024; i += 256) s1[i] = c1p[i];
        for (int i = tid; i < 128; i += 256) s2[i] = c2p[i];
        __syncthreads();
        for (int e = tid; e < 4096; e += 256) {
            int i = e >> 6, j = e & 63;
            int i1 = i >> 4, i2 = (i >> 2) & 3, i3 = i & 3;
            int j1 = j >> 4, j2 = (j >> 2) & 3, j3 = j & 3;
            float s = 0.f;
            #pragma unroll
            for (int r1 = 0; r1 < 8; ++r1) {
                float a = s0[(i1 * 4 + j1) * 8 + r1];
                float t = 0.f;
                #pragma unroll
                for (int r2 = 0; r2 < 8; ++r2)
                    t += s1[((r1 * 4 + i2) * 4 + j2) * 8 + r2] * s2[(r2 * 4 + i3) * 4 + j3];
                s = fmaf(a, t, s);
            }
            g_Wm[e] = s;
        }
        return;
    }

    int bi = blockIdx.x >> 3;
    int strip = blockIdx.x & 7;
    int r0 = strip * 8;

    // zero the whole A region (covers the w=64..67 pads)
    for (int i = tid; i < 43520 / 16; i += 256)
        *reinterpret_cast<uint4*>(smem + i * 16) = make_uint4(0, 0, 0, 0);

    // B fill: ker flat [co][cin][kh][kw] -> [tap][cin][co] hi/lo, swizzled
    for (int idx = tid; idx < 2304; idx += 256) {
        int co = idx / 144, rem = idx % 144;
        int cin = rem / 9, kk = rem % 9;
        unsigned short h, l;
        bsplit16(ker[idx], h, l);
        uint32_t raw = (uint32_t)kk * 512 + cin * 32 + co * 2;
        uint32_t sw = SWZ(raw);
        *reinterpret_cast<unsigned short*>(smem + B_SM + sw) = h;
        *reinterpret_cast<unsigned short*>(smem + B_SM + 4608 + sw) = l;
    }
    __syncthreads();  // zero-fill must land before A fill overwrites

    // A fill: x[cin][row][w] fp32 -> smem [row][w][cin] bf16 hi/lo, swizzled
    const float* xb = x + (size_t)bi * (16 * 64 * 64);
    for (int idx = tid; idx < 16 * 10 * 64; idx += 256) {
        int w = idx & 63;
        int rr = (idx >> 6) % 10;
        int c = idx / 640;
        int rg = r0 + rr; if (rg > 63) rg = 63;
        unsigned short h, l;
        bsplit16(xb[(c * 64 + rg) * 64 + w], h, l);
        uint32_t raw = (uint32_t)rr * 2176 + w * 32 + c * 2;
        uint32_t sw = SWZ(raw);
        *reinterpret_cast<unsigned short*>(smem + A_HI + sw) = h;
        *reinterpret_cast<unsigned short*>(smem + A_LO + sw) = l;
    }
    __syncthreads();

    int lane = tid & 31;
    int warp = tid >> 5;          // output row within strip
    int h = r0 + warp;

    float acc[4][2][4];
    #pragma unroll
    for (int wt = 0; wt < 4; ++wt)
        #pragma unroll
        for (int f = 0; f < 2; ++f)
            #pragma unroll
            for (int e = 0; e < 4; ++e) acc[wt][f][e] = 0.f;

    int arow = lane & 15;
    int khalf = (lane >> 4) * 16;

    #pragma unroll
    for (int kh = 0; kh < 3; ++kh) {
        #pragma unroll
        for (int kw = 0; kw < 3; ++kw) {
            int tap = kh * 3 + kw;
            uint32_t brw = (uint32_t)tap * 512 + arow * 32 + khalf;
            uint32_t baddr = sb + B_SM + SWZ(brw);
            uint32_t bh[4], bl[4];
            LDSM_X4T(bh[0], bh[1], bh[2], bh[3], baddr);
            LDSM_X4T(bl[0], bl[1], bl[2], bl[3], baddr + 4608);

            uint32_t rbase = (uint32_t)(warp + kh) * 2176;
            #pragma unroll
            for (int wt = 0; wt < 4; ++wt) {
                uint32_t araw = rbase + (wt * 16 + arow + kw) * 32 + khalf;
                uint32_t aaddr = sb + SWZ(araw);
                uint32_t ahi[4], alo[4];
                LDSM_X4(ahi[0], ahi[1], ahi[2], ahi[3], aaddr + A_HI);
                LDSM_X4(alo[0], alo[1], alo[2], alo[3], aaddr + A_LO);
                #pragma unroll
                for (int f = 0; f < 2; ++f) {
                    mma16816(acc[wt][f], ahi, bh[2 * f], bh[2 * f + 1]);
                    mma16816(acc[wt][f], ahi, bl[2 * f], bl[2 * f + 1]);
                    mma16816(acc[wt][f], alo, bh[2 * f], bh[2 * f + 1]);
                }
            }
        }
    }

    __syncthreads();  // all A reads done; alias stage buffer onto A region

    // stage: stg[row 8][co 16][w 68] floats (pitch 68 -> conflict-free writes)
    float* stg = reinterpret_cast<float*>(smem);
    {
        int wl = lane >> 2;
        int cl = (lane & 3) * 2;
        #pragma unroll
        for (int wt = 0; wt < 4; ++wt)
            #pragma unroll
            for (int f = 0; f < 2; ++f) {
                int w_a = wt * 16 + wl;
                int co = f * 8 + cl;
                float* p0 = &stg[(warp * 16 + co) * 68 + w_a];
                p0[0]   = acc[wt][f][0];
                p0[68]  = acc[wt][f][1];
                p0[8]   = acc[wt][f][2];
                p0[76]  = acc[wt][f][3];
            }
    }
    __syncthreads();

    // coalesced store to g_y[bi][co][h][w]
    float* yb = g_y + (size_t)bi * (16 * 62 * 62);
    for (int idx = tid; idx < 8 * 16 * 62; idx += 256) {
        int w = idx % 62;
        int co = (idx / 62) & 15;
        int row = idx / 992;
        int hg = r0 + row;
        if (hg < 62)
            yb[(co * 62 + hg) * 62 + w] = stg[(row * 16 + co) * 68 + w];
    }
}

// ---------------------------------------------------------------------------
// Kernel 2: mix via mma.sync bf16 split (UNCHANGED from R6).
// ---------------------------------------------------------------------------
static constexpr int PITCH = 144;
static constexpr int SM_AHI  = 0;
static constexpr int SM_ALO  = 18432;
static constexpr int SM_BHI  = 36864;
static constexpr int SM_BLO  = 46080;
static constexpr int SM_BIAS = 55296;
static constexpr int SM_MIX  = 55552;

__global__ __launch_bounds__(256) void mix_mma_kernel(const float* __restrict__ bias,
                                                      float* __restrict__ out) {
    extern __shared__ __align__(16) char smem[];
    uint32_t sb = smem_u32(smem);
    int tid = threadIdx.x;
    int lane = tid & 31;
    int warp = tid >> 5;
    int co = blockIdx.y;
    int b  = blockIdx.z;
    int p_base = blockIdx.x * 128;

    if (tid < 128) {
        int i = tid & 63;
        int jh = tid >> 6;
        int j0 = jh * 32;
        const float4* src = reinterpret_cast<const float4*>(&g_Wm[i * 64 + j0]);
        uint32_t base = sb + i * PITCH + j0 * 2;
        #pragma unroll
        for (int q = 0; q < 4; ++q) {
            float4 v0 = src[2 * q];
            float4 v1 = src[2 * q + 1];
            uint32_t l0, l1, l2, l3;
            uint32_t h0 = bsplit_pack_hi(v0.x, v0.y, l0);
            uint32_t h1 = bsplit_pack_hi(v0.z, v0.w, l1);
            uint32_t h2 = bsplit_pack_hi(v1.x, v1.y, l2);
            uint32_t h3 = bsplit_pack_hi(v1.z, v1.w, l3);
            STS128(base + SM_BHI + q * 16, h0, h1, h2, h3);
            STS128(base + SM_BLO + q * 16, l0, l1, l2, l3);
        }
    }
    if (tid < 64)
        *reinterpret_cast<float*>(smem + SM_BIAS + tid * 4) = bias[tid];

    {
        int p = tid & 127;
        int ih = tid >> 7;
        int i0 = ih * 32;
        int pg = p_base + p;
        bool pok = pg < 3844;
        const float* ybase = g_y + ((size_t)(b * 64 + i0) * 16 + co) * 3844 + pg;
        uint32_t base = sb + p * PITCH + i0 * 2;
        #pragma unroll
        for (int s = 0; s < 4; ++s) {
            float v[8];
            #pragma unroll
            for (int e = 0; e < 8; ++e)
                v[e] = pok ? ybase[(size_t)(s * 8 + e) * (16 * 3844)] : 0.f;
            uint32_t l0, l1, l2, l3;
            uint32_t h0 = bsplit_pack_hi(v[0], v[1], l0);
            uint32_t h1 = bsplit_pack_hi(v[2], v[3], l1);
            uint32_t h2 = bsplit_pack_hi(v[4], v[5], l2);
            uint32_t h3 = bsplit_pack_hi(v[6], v[7], l3);
            STS128(base + SM_AHI + s * 16, h0, h1, h2, h3);
            STS128(base + SM_ALO + s * 16, l0, l1, l2, l3);
        }
    }
    __syncthreads();

    float acc[8][4];
    #pragma unroll
    for (int nt = 0; nt < 8; ++nt)
        #pragma unroll
        for (int e = 0; e < 4; ++e) acc[nt][e] = 0.f;

    uint32_t a_row = warp * 16 + (lane & 15);
    uint32_t a_off = sb + a_row * PITCH + (lane >> 4) * 16;
    uint32_t b_kr = (lane & 15);
    uint32_t b_jc = (lane >> 4) * 8;

    #pragma unroll
    for (int k = 0; k < 4; ++k) {
        uint32_t ahi[4], alo[4];
        LDSM_X4(ahi[0], ahi[1], ahi[2], ahi[3], a_off + SM_AHI + k * 32);
        LDSM_X4(alo[0], alo[1], alo[2], alo[3], a_off + SM_ALO + k * 32);

        #pragma unroll
        for (int jp = 0; jp < 4; ++jp) {
            uint32_t baddr = sb + (k * 16 + b_kr) * PITCH + (jp * 16 + b_jc) * 2;
            uint32_t bh[4], bl[4];
            LDSM_X4T(bh[0], bh[1], bh[2], bh[3], baddr + SM_BHI);
            LDSM_X4T(bl[0], bl[1], bl[2], bl[3], baddr + SM_BLO);
            mma16816(acc[2 * jp], ahi, bh[0], bh[1]);
            mma16816(acc[2 * jp], ahi, bl[0], bl[1]);
            mma16816(acc[2 * jp], alo, bh[0], bh[1]);
            mma16816(acc[2 * jp + 1], ahi, bh[2], bh[3]);
            mma16816(acc[2 * jp + 1], ahi, bl[2], bl[3]);
            mma16816(acc[2 * jp + 1], alo, bh[2], bh[3]);
        }
    }

    size_t rowbase = (size_t)(b * 16 + co) * 3844;
    int row0 = warp * 16 + (lane >> 2);
    int pm0 = p_base + row0;
    int pm1 = pm0 + 8;
    int jsub = (lane & 3) * 2;

    #pragma unroll
    for (int nt = 0; nt < 8; ++nt) {
        int j = nt * 8 + jsub;
        float2 bv = *reinterpret_cast<const float2*>(smem + SM_BIAS + j * 4);
        if (pm0 < 3844)
            *reinterpret_cast<float2*>(&out[(rowbase + pm0) * 64 + j]) =
                make_float2(acc[nt][0] + bv.x, acc[nt][1] + bv.y);
        if (pm1 < 3844)
            *reinterpret_cast<float2*>(&out[(rowbase + pm1) * 64 + j]) =
                make_float2(acc[nt][2] + bv.x, acc[nt][3] + bv.y);
    }
}

// ---------------------------------------------------------------------------
extern "C" void kernel_launch(void* const* d_in, const int* in_sizes, int n_in,
                              void* d_out, int out_size) {
    const float* x    = (const float*)d_in[0];
    const float* ker  = (const float*)d_in[1];
    const float* c0   = (const float*)d_in[2];
    const float* c1   = (const float*)d_in[3];
    const float* c2   = (const float*)d_in[4];
    const float* bias = (const float*)d_in[5];
    float* out = (float*)d_out;

    cudaFuncSetAttribute(conv_tc_kernel,
                         cudaFuncAttributeMaxDynamicSharedMemorySize, SM_CONV);
    cudaFuncSetAttribute(mix_mma_kernel,
                         cudaFuncAttributeMaxDynamicSharedMemorySize, SM_MIX);

    conv_tc_kernel<<<4097, 256, SM_CONV>>>(x, ker, c0, c1, c2);
    mix_mma_kernel<<<dim3(31, 16, 8), 256, SM_MIX>>>(bias, out);
}

// round 8
// speedup vs baseline: 1.9850x; 1.1931x over previous
#include <cuda_runtime.h>
#include <cuda_bf16.h>
#include <cstdint>

typedef unsigned long long u64;

// ---------------------------------------------------------------------------
// Tensor-core helpers (baseline PTX: ldmatrix sm_75+, mma.sync sm_80+)
// ---------------------------------------------------------------------------
__device__ __forceinline__ uint32_t smem_u32(const void* p) {
    uint32_t a;
    asm("{ .reg .u64 t; cvta.to.shared.u64 t, %1; cvt.u32.u64 %0, t; }" : "=r"(a) : "l"(p));
    return a;
}

#define LDSM_X4(r0, r1, r2, r3, a) \
    asm volatile("ldmatrix.sync.aligned.m8n8.x4.shared.b16 {%0,%1,%2,%3}, [%4];" \
        : "=r"(r0), "=r"(r1), "=r"(r2), "=r"(r3) : "r"(a))
#define LDSM_X4T(r0, r1, r2, r3, a) \
    asm volatile("ldmatrix.sync.aligned.m8n8.x4.trans.shared.b16 {%0,%1,%2,%3}, [%4];" \
        : "=r"(r0), "=r"(r1), "=r"(r2), "=r"(r3) : "r"(a))

__device__ __forceinline__ void mma16816(float* d, const uint32_t* a,
                                         uint32_t b0, uint32_t b1) {
    asm volatile(
        "mma.sync.aligned.m16n8k16.row.col.f32.bf16.bf16.f32 "
        "{%0,%1,%2,%3}, {%4,%5,%6,%7}, {%8,%9}, {%0,%1,%2,%3};"
        : "+f"(d[0]), "+f"(d[1]), "+f"(d[2]), "+f"(d[3])
        : "r"(a[0]), "r"(a[1]), "r"(a[2]), "r"(a[3]), "r"(b0), "r"(b1));
}

__device__ __forceinline__ void bsplit16(float v, unsigned short& h, unsigned short& l) {
    __nv_bfloat16 bh = __float2bfloat16_rn(v);
    __nv_bfloat16 bl = __float2bfloat16_rn(v - __bfloat162float(bh));
    h = __bfloat16_as_ushort(bh);
    l = __bfloat16_as_ushort(bl);
}

__device__ __forceinline__ uint32_t bsplit_pack_hi(float v0, float v1, uint32_t& lo) {
    __nv_bfloat16 h0 = __float2bfloat16_rn(v0);
    __nv_bfloat16 h1 = __float2bfloat16_rn(v1);
    __nv_bfloat16 l0 = __float2bfloat16_rn(v0 - __bfloat162float(h0));
    __nv_bfloat16 l1 = __float2bfloat16_rn(v1 - __bfloat162float(h1));
    lo = (uint32_t)__bfloat16_as_ushort(l0) | ((uint32_t)__bfloat16_as_ushort(l1) << 16);
    return (uint32_t)__bfloat16_as_ushort(h0) | ((uint32_t)__bfloat16_as_ushort(h1) << 16);
}

#define STS128(a, r0, r1, r2, r3) \
    asm volatile("st.shared.v4.b32 [%0], {%1,%2,%3,%4};" :: "r"(a), "r"(r0), "r"(r1), "r"(r2), "r"(r3) : "memory")

// swizzle: flip the 16B slot when bit7 set -> 8 consecutive w pixels (32B
// stride) occupy 8 distinct 16B slots => ldmatrix conflict-free.
#define SWZ(a) ((a) ^ (((a) >> 3) & 0x10))

// ---------------------------------------------------------------------------
// Scratch
// ---------------------------------------------------------------------------
static __device__ float g_Wm[64 * 64];
static __device__ float g_y[512u * 16u * 62u * 62u];

// ---------------------------------------------------------------------------
// Kernel 1: tensor-core conv. grid = 512 images x 8 row-strips (+1 Wm block).
// 256 thr = 8 warps; warp = one output row; 4 m16 w-tiles x n16 co.
// A = x [row 10][w 68][cin 16] bf16 hi/lo (swizzled); B = ker [tap][cin][co].
// 9 shifted-tap GEMMs, K=16 each, bf16 split (hh + hl + lh).
// A-fill: thread = (row, w) packs all 16 cin -> 2 conflict-free STS.128 per
// buffer (R7's scalar STS.U16 fill was 8-way bank-conflicted).
// ---------------------------------------------------------------------------
static constexpr int A_HI = 0;          // 10 * 2176 = 21760
static constexpr int A_LO = 21760;      // 21760
static constexpr int B_SM = 43520;      // 9 * 512 * 2 = 9216
static constexpr int SM_CONV = 52736;

__global__ __launch_bounds__(256) void conv_tc_kernel(const float* __restrict__ x,
                                                      const float* __restrict__ ker,
                                                      const float* __restrict__ c0p,
                                                      const float* __restrict__ c1p,
                                                      const float* __restrict__ c2p) {
    extern __shared__ __align__(128) char smem[];
    uint32_t sb = smem_u32(smem);
    int tid = threadIdx.x;

    if (blockIdx.x == 4096) {
        // ---- TT-matrix reconstruction (hidden under the conv wave) ----
        float* s0 = reinterpret_cast<float*>(smem);
        float* s1 = s0 + 128;
        float* s2 = s1 + 1024;
        for (int i = tid; i < 128; i += 256) s0[i] = c0p[i];
        for (int i = tid; i < 1024; i += 256) s1[i] = c1p[i];
        for (int i = tid; i < 128; i += 256) s2[i] = c2p[i];
        __syncthreads();
        for (int e = tid; e < 4096; e += 256) {
            int i = e >> 6, j = e & 63;
            int i1 = i >> 4, i2 = (i >> 2) & 3, i3 = i & 3;
            int j1 = j >> 4, j2 = (j >> 2) & 3, j3 = j & 3;
            float s = 0.f;
            #pragma unroll
            for (int r1 = 0; r1 < 8; ++r1) {
                float a = s0[(i1 * 4 + j1) * 8 + r1];
                float t = 0.f;
                #pragma unroll
                for (int r2 = 0; r2 < 8; ++r2)
                    t += s1[((r1 * 4 + i2) * 4 + j2) * 8 + r2] * s2[(r2 * 4 + i3) * 4 + j3];
                s = fmaf(a, t, s);
            }
            g_Wm[e] = s;
        }
        return;
    }

    int bi = blockIdx.x >> 3;
    int strip = blockIdx.x & 7;
    int r0 = strip * 8;

    // zero ONLY the w=64..67 pad slots (both buffers, all rows)
    for (int idx = tid; idx < 160; idx += 256) {
        int bsel  = idx & 1;
        int chunk = (idx >> 1) & 1;
        int w  = 64 + ((idx >> 2) & 3);
        int rr = idx >> 4;                 // 0..9
        uint32_t raw = (uint32_t)rr * 2176 + w * 32 + chunk * 16;
        uint32_t a = SWZ(raw) + (bsel ? A_LO : A_HI);
        STS128(sb + a, 0u, 0u, 0u, 0u);
    }

    // B fill: ker flat [co][cin][kh][kw] -> [tap][cin][co] hi/lo, swizzled
    for (int idx = tid; idx < 2304; idx += 256) {
        int co = idx / 144, rem = idx % 144;
        int cin = rem / 9, kk = rem % 9;
        unsigned short h, l;
        bsplit16(ker[idx], h, l);
        uint32_t raw = (uint32_t)kk * 512 + cin * 32 + co * 2;
        uint32_t sw = SWZ(raw);
        *reinterpret_cast<unsigned short*>(smem + B_SM + sw) = h;
        *reinterpret_cast<unsigned short*>(smem + B_SM + 4608 + sw) = l;
    }

    // A fill: thread = (row, w); pack 16 cin -> 2x STS.128 per buffer.
    const float* xb = x + (size_t)bi * (16 * 64 * 64);
    for (int idx = tid; idx < 640; idx += 256) {
        int w  = idx & 63;
        int rr = idx >> 6;
        int rg = r0 + rr; if (rg > 63) rg = 63;
        const float* src = xb + rg * 64 + w;
        uint32_t ph[8], pl[8];
        #pragma unroll
        for (int e = 0; e < 8; ++e) {
            float v0 = src[(size_t)(2 * e) * 4096];
            float v1 = src[(size_t)(2 * e + 1) * 4096];
            ph[e] = bsplit_pack_hi(v0, v1, pl[e]);
        }
        uint32_t raw0 = (uint32_t)rr * 2176 + w * 32;
        uint32_t a0 = SWZ(raw0);
        uint32_t a1 = SWZ(raw0 + 16);
        STS128(sb + A_HI + a0, ph[0], ph[1], ph[2], ph[3]);
        STS128(sb + A_HI + a1, ph[4], ph[5], ph[6], ph[7]);
        STS128(sb + A_LO + a0, pl[0], pl[1], pl[2], pl[3]);
        STS128(sb + A_LO + a1, pl[4], pl[5], pl[6], pl[7]);
    }
    __syncthreads();

    int lane = tid & 31;
    int warp = tid >> 5;          // output row within strip
    int h = r0 + warp;

    float acc[4][2][4];
    #pragma unroll
    for (int wt = 0; wt < 4; ++wt)
        #pragma unroll
        for (int f = 0; f < 2; ++f)
            #pragma unroll
            for (int e = 0; e < 4; ++e) acc[wt][f][e] = 0.f;

    int arow = lane & 15;
    int khalf = (lane >> 4) * 16;

    #pragma unroll
    for (int kh = 0; kh < 3; ++kh) {
        #pragma unroll
        for (int kw = 0; kw < 3; ++kw) {
            int tap = kh * 3 + kw;
            uint32_t brw = (uint32_t)tap * 512 + arow * 32 + khalf;
            uint32_t baddr = sb + B_SM + SWZ(brw);
            uint32_t bh[4], bl[4];
            LDSM_X4T(bh[0], bh[1], bh[2], bh[3], baddr);
            LDSM_X4T(bl[0], bl[1], bl[2], bl[3], baddr + 4608);

            uint32_t rbase = (uint32_t)(warp + kh) * 2176;
            #pragma unroll
            for (int wt = 0; wt < 4; ++wt) {
                uint32_t araw = rbase + (wt * 16 + arow + kw) * 32 + khalf;
                uint32_t aaddr = sb + SWZ(araw);
                uint32_t ahi[4], alo[4];
                LDSM_X4(ahi[0], ahi[1], ahi[2], ahi[3], aaddr + A_HI);
                LDSM_X4(alo[0], alo[1], alo[2], alo[3], aaddr + A_LO);
                #pragma unroll
                for (int f = 0; f < 2; ++f) {
                    mma16816(acc[wt][f], ahi, bh[2 * f], bh[2 * f + 1]);
                    mma16816(acc[wt][f], ahi, bl[2 * f], bl[2 * f + 1]);
                    mma16816(acc[wt][f], alo, bh[2 * f], bh[2 * f + 1]);
                }
            }
        }
    }

    __syncthreads();  // all A reads done; alias stage buffer onto A region

    // stage: stg[row 8][co 16][w 68] floats (conflict-free writes)
    float* stg = reinterpret_cast<float*>(smem);
    {
        int wl = lane >> 2;
        int cl = (lane & 3) * 2;
        #pragma unroll
        for (int wt = 0; wt < 4; ++wt)
            #pragma unroll
            for (int f = 0; f < 2; ++f) {
                int w_a = wt * 16 + wl;
                int co = f * 8 + cl;
                float* p0 = &stg[(warp * 16 + co) * 68 + w_a];
                p0[0]   = acc[wt][f][0];
                p0[68]  = acc[wt][f][1];
                p0[8]   = acc[wt][f][2];
                p0[76]  = acc[wt][f][3];
            }
    }
    __syncthreads();

    // coalesced store to g_y[bi][co][h][w]
    float* yb = g_y + (size_t)bi * (16 * 62 * 62);
    for (int idx = tid; idx < 8 * 16 * 62; idx += 256) {
        int w = idx % 62;
        int co = (idx / 62) & 15;
        int row = idx / 992;
        int hg = r0 + row;
        if (hg < 62)
            yb[(co * 62 + hg) * 62 + w] = stg[(row * 16 + co) * 68 + w];
    }
}

// ---------------------------------------------------------------------------
// Kernel 2: mix via mma.sync bf16 split (UNCHANGED from R6/R7).
// ---------------------------------------------------------------------------
static constexpr int PITCH = 144;
static constexpr int SM_AHI  = 0;
static constexpr int SM_ALO  = 18432;
static constexpr int SM_BHI  = 36864;
static constexpr int SM_BLO  = 46080;
static constexpr int SM_BIAS = 55296;
static constexpr int SM_MIX  = 55552;

__global__ __launch_bounds__(256) void mix_mma_kernel(const float* __restrict__ bias,
                                                      float* __restrict__ out) {
    extern __shared__ __align__(16) char smem[];
    uint32_t sb = smem_u32(smem);
    int tid = threadIdx.x;
    int lane = tid & 31;
    int warp = tid >> 5;
    int co = blockIdx.y;
    int b  = blockIdx.z;
    int p_base = blockIdx.x * 128;

    if (tid < 128) {
        int i = tid & 63;
        int jh = tid >> 6;
        int j0 = jh * 32;
        const float4* src = reinterpret_cast<const float4*>(&g_Wm[i * 64 + j0]);
        uint32_t base = sb + i * PITCH + j0 * 2;
        #pragma unroll
        for (int q = 0; q < 4; ++q) {
            float4 v0 = src[2 * q];
            float4 v1 = src[2 * q + 1];
            uint32_t l0, l1, l2, l3;
            uint32_t h0 = bsplit_pack_hi(v0.x, v0.y, l0);
            uint32_t h1 = bsplit_pack_hi(v0.z, v0.w, l1);
            uint32_t h2 = bsplit_pack_hi(v1.x, v1.y, l2);
            uint32_t h3 = bsplit_pack_hi(v1.z, v1.w, l3);
            STS128(base + SM_BHI + q * 16, h0, h1, h2, h3);
            STS128(base + SM_BLO + q * 16, l0, l1, l2, l3);
        }
    }
    if (tid < 64)
        *reinterpret_cast<float*>(smem + SM_BIAS + tid * 4) = bias[tid];

    {
        int p = tid & 127;
        int ih = tid >> 7;
        int i0 = ih * 32;
        int pg = p_base + p;
        bool pok = pg < 3844;
        const float* ybase = g_y + ((size_t)(b * 64 + i0) * 16 + co) * 3844 + pg;
        uint32_t base = sb + p * PITCH + i0 * 2;
        #pragma unroll
        for (int s = 0; s < 4; ++s) {
            float v[8];
            #pragma unroll
            for (int e = 0; e < 8; ++e)
                v[e] = pok ? ybase[(size_t)(s * 8 + e) * (16 * 3844)] : 0.f;
            uint32_t l0, l1, l2, l3;
            uint32_t h0 = bsplit_pack_hi(v[0], v[1], l0);
            uint32_t h1 = bsplit_pack_hi(v[2], v[3], l1);
            uint32_t h2 = bsplit_pack_hi(v[4], v[5], l2);
            uint32_t h3 = bsplit_pack_hi(v[6], v[7], l3);
            STS128(base + SM_AHI + s * 16, h0, h1, h2, h3);
            STS128(base + SM_ALO + s * 16, l0, l1, l2, l3);
        }
    }
    __syncthreads();

    float acc[8][4];
    #pragma unroll
    for (int nt = 0; nt < 8; ++nt)
        #pragma unroll
        for (int e = 0; e < 4; ++e) acc[nt][e] = 0.f;

    uint32_t a_row = warp * 16 + (lane & 15);
    uint32_t a_off = sb + a_row * PITCH + (lane >> 4) * 16;
    uint32_t b_kr = (lane & 15);
    uint32_t b_jc = (lane >> 4) * 8;

    #pragma unroll
    for (int k = 0; k < 4; ++k) {
        uint32_t ahi[4], alo[4];
        LDSM_X4(ahi[0], ahi[1], ahi[2], ahi[3], a_off + SM_AHI + k * 32);
        LDSM_X4(alo[0], alo[1], alo[2], alo[3], a_off + SM_ALO + k * 32);

        #pragma unroll
        for (int jp = 0; jp < 4; ++jp) {
            uint32_t baddr = sb + (k * 16 + b_kr) * PITCH + (jp * 16 + b_jc) * 2;
            uint32_t bh[4], bl[4];
            LDSM_X4T(bh[0], bh[1], bh[2], bh[3], baddr + SM_BHI);
            LDSM_X4T(bl[0], bl[1], bl[2], bl[3], baddr + SM_BLO);
            mma16816(acc[2 * jp], ahi, bh[0], bh[1]);
            mma16816(acc[2 * jp], ahi, bl[0], bl[1]);
            mma16816(acc[2 * jp], alo, bh[0], bh[1]);
            mma16816(acc[2 * jp + 1], ahi, bh[2], bh[3]);
            mma16816(acc[2 * jp + 1], ahi, bl[2], bl[3]);
            mma16816(acc[2 * jp + 1], alo, bh[2], bh[3]);
        }
    }

    size_t rowbase = (size_t)(b * 16 + co) * 3844;
    int row0 = warp * 16 + (lane >> 2);
    int pm0 = p_base + row0;
    int pm1 = pm0 + 8;
    int jsub = (lane & 3) * 2;

    #pragma unroll
    for (int nt = 0; nt < 8; ++nt) {
        int j = nt * 8 + jsub;
        float2 bv = *reinterpret_cast<const float2*>(smem + SM_BIAS + j * 4);
        if (pm0 < 3844)
            *reinterpret_cast<float2*>(&out[(rowbase + pm0) * 64 + j]) =
                make_float2(acc[nt][0] + bv.x, acc[nt][1] + bv.y);
        if (pm1 < 3844)
            *reinterpret_cast<float2*>(&out[(rowbase + pm1) * 64 + j]) =
                make_float2(acc[nt][2] + bv.x, acc[nt][3] + bv.y);
    }
}

// ---------------------------------------------------------------------------
extern "C" void kernel_launch(void* const* d_in, const int* in_sizes, int n_in,
                              void* d_out, int out_size) {
    const float* x    = (const float*)d_in[0];
    const float* ker  = (const float*)d_in[1];
    const float* c0   = (const float*)d_in[2];
    const float* c1   = (const float*)d_in[3];
    const float* c2   = (const float*)d_in[4];
    const float* bias = (const float*)d_in[5];
    float* out = (float*)d_out;

    cudaFuncSetAttribute(conv_tc_kernel,
                         cudaFuncAttributeMaxDynamicSharedMemorySize, SM_CONV);
    cudaFuncSetAttribute(mix_mma_kernel,
                         cudaFuncAttributeMaxDynamicSharedMemorySize, SM_MIX);

    conv_tc_kernel<<<4097, 256, SM_CONV>>>(x, ker, c0, c1, c2);
    mix_mma_kernel<<<dim3(31, 16, 8), 256, SM_MIX>>>(bias, out);
}

// round 9
// speedup vs baseline: 2.0733x; 1.0445x over previous
#include <cuda_runtime.h>
#include <cuda_bf16.h>
#include <cstdint>

typedef unsigned long long u64;

// ---------------------------------------------------------------------------
// Tensor-core helpers (baseline PTX: ldmatrix sm_75+, mma.sync sm_80+)
// ---------------------------------------------------------------------------
__device__ __forceinline__ uint32_t smem_u32(const void* p) {
    uint32_t a;
    asm("{ .reg .u64 t; cvta.to.shared.u64 t, %1; cvt.u32.u64 %0, t; }" : "=r"(a) : "l"(p));
    return a;
}

#define LDSM_X4(r0, r1, r2, r3, a) \
    asm volatile("ldmatrix.sync.aligned.m8n8.x4.shared.b16 {%0,%1,%2,%3}, [%4];" \
        : "=r"(r0), "=r"(r1), "=r"(r2), "=r"(r3) : "r"(a))
#define LDSM_X4T(r0, r1, r2, r3, a) \
    asm volatile("ldmatrix.sync.aligned.m8n8.x4.trans.shared.b16 {%0,%1,%2,%3}, [%4];" \
        : "=r"(r0), "=r"(r1), "=r"(r2), "=r"(r3) : "r"(a))

__device__ __forceinline__ void mma16816(float* d, const uint32_t* a,
                                         uint32_t b0, uint32_t b1) {
    asm volatile(
        "mma.sync.aligned.m16n8k16.row.col.f32.bf16.bf16.f32 "
        "{%0,%1,%2,%3}, {%4,%5,%6,%7}, {%8,%9}, {%0,%1,%2,%3};"
        : "+f"(d[0]), "+f"(d[1]), "+f"(d[2]), "+f"(d[3])
        : "r"(a[0]), "r"(a[1]), "r"(a[2]), "r"(a[3]), "r"(b0), "r"(b1));
}

__device__ __forceinline__ void bsplit16(float v, unsigned short& h, unsigned short& l) {
    __nv_bfloat16 bh = __float2bfloat16_rn(v);
    __nv_bfloat16 bl = __float2bfloat16_rn(v - __bfloat162float(bh));
    h = __bfloat16_as_ushort(bh);
    l = __bfloat16_as_ushort(bl);
}

__device__ __forceinline__ uint32_t bsplit_pack_hi(float v0, float v1, uint32_t& lo) {
    __nv_bfloat16 h0 = __float2bfloat16_rn(v0);
    __nv_bfloat16 h1 = __float2bfloat16_rn(v1);
    __nv_bfloat16 l0 = __float2bfloat16_rn(v0 - __bfloat162float(h0));
    __nv_bfloat16 l1 = __float2bfloat16_rn(v1 - __bfloat162float(h1));
    lo = (uint32_t)__bfloat16_as_ushort(l0) | ((uint32_t)__bfloat16_as_ushort(l1) << 16);
    return (uint32_t)__bfloat16_as_ushort(h0) | ((uint32_t)__bfloat16_as_ushort(h1) << 16);
}

#define STS128(a, r0, r1, r2, r3) \
    asm volatile("st.shared.v4.b32 [%0], {%1,%2,%3,%4};" :: "r"(a), "r"(r0), "r"(r1), "r"(r2), "r"(r3) : "memory")

// swizzle: flip the 16B slot when bit7 set -> 8 consecutive w pixels (32B
// stride) occupy 8 distinct 16B slots => ldmatrix conflict-free.
#define SWZ(a) ((a) ^ (((a) >> 3) & 0x10))

// ---------------------------------------------------------------------------
// Scratch
// ---------------------------------------------------------------------------
static __device__ float g_Wm[64 * 64];
static __device__ float g_y[512u * 16u * 62u * 62u];

// ---------------------------------------------------------------------------
// Kernel 1: tensor-core conv. grid = 512 images x 4 row-strips (+1 Wm block).
// 512 thr = 16 warps; warp = one output row (16-row strips, 18-row halo).
// A = x [row 18][w 68][cin 16] bf16 hi/lo (swizzled); B = ker [tap][cin][co].
// 9 shifted-tap GEMMs, K=16 each, bf16 split (hh + hl + lh).
// ---------------------------------------------------------------------------
static constexpr int A_HI = 0;          // 18 * 2176 = 39168
static constexpr int A_LO = 39168;      // 39168
static constexpr int B_SM = 78336;      // 9 * 512 * 2 = 9216
static constexpr int SM_CONV = 87552;

__global__ __launch_bounds__(512) void conv_tc_kernel(const float* __restrict__ x,
                                                      const float* __restrict__ ker,
                                                      const float* __restrict__ c0p,
                                                      const float* __restrict__ c1p,
                                                      const float* __restrict__ c2p) {
    extern __shared__ __align__(128) char smem[];
    uint32_t sb = smem_u32(smem);
    int tid = threadIdx.x;

    if (blockIdx.x == 2048) {
        // ---- TT-matrix reconstruction (hidden under the conv wave) ----
        float* s0 = reinterpret_cast<float*>(smem);
        float* s1 = s0 + 128;
        float* s2 = s1 + 1024;
        for (int i = tid; i < 128; i += 512) s0[i] = c0p[i];
        for (int i = tid; i < 1024; i += 512) s1[i] = c1p[i];
        for (int i = tid; i < 128; i += 512) s2[i] = c2p[i];
        __syncthreads();
        for (int e = tid; e < 4096; e += 512) {
            int i = e >> 6, j = e & 63;
            int i1 = i >> 4, i2 = (i >> 2) & 3, i3 = i & 3;
            int j1 = j >> 4, j2 = (j >> 2) & 3, j3 = j & 3;
            float s = 0.f;
            #pragma unroll
            for (int r1 = 0; r1 < 8; ++r1) {
                float a = s0[(i1 * 4 + j1) * 8 + r1];
                float t = 0.f;
                #pragma unroll
                for (int r2 = 0; r2 < 8; ++r2)
                    t += s1[((r1 * 4 + i2) * 4 + j2) * 8 + r2] * s2[(r2 * 4 + i3) * 4 + j3];
                s = fmaf(a, t, s);
            }
            g_Wm[e] = s;
        }
        return;
    }

    int bi = blockIdx.x >> 2;
    int strip = blockIdx.x & 3;
    int r0 = strip * 16;

    // zero ONLY the w=64..67 pad slots (both buffers, 18 rows)
    for (int idx = tid; idx < 288; idx += 512) {
        int bsel  = idx & 1;
        int chunk = (idx >> 1) & 1;
        int w  = 64 + ((idx >> 2) & 3);
        int rr = idx >> 4;                 // 0..17
        uint32_t raw = (uint32_t)rr * 2176 + w * 32 + chunk * 16;
        uint32_t a = SWZ(raw) + (bsel ? A_LO : A_HI);
        STS128(sb + a, 0u, 0u, 0u, 0u);
    }

    // B fill: ker flat [co][cin][kh][kw] -> [tap][cin][co] hi/lo, swizzled
    for (int idx = tid; idx < 2304; idx += 512) {
        int co = idx / 144, rem = idx % 144;
        int cin = rem / 9, kk = rem % 9;
        unsigned short h, l;
        bsplit16(ker[idx], h, l);
        uint32_t raw = (uint32_t)kk * 512 + cin * 32 + co * 2;
        uint32_t sw = SWZ(raw);
        *reinterpret_cast<unsigned short*>(smem + B_SM + sw) = h;
        *reinterpret_cast<unsigned short*>(smem + B_SM + 4608 + sw) = l;
    }

    // A fill: thread = (row, w); pack 16 cin -> 2x STS.128 per buffer.
    const float* xb = x + (size_t)bi * (16 * 64 * 64);
    for (int idx = tid; idx < 1152; idx += 512) {
        int w  = idx & 63;
        int rr = idx >> 6;                 // 0..17
        int rg = r0 + rr; if (rg > 63) rg = 63;
        const float* src = xb + rg * 64 + w;
        uint32_t ph[8], pl[8];
        #pragma unroll
        for (int e = 0; e < 8; ++e) {
            float v0 = src[(size_t)(2 * e) * 4096];
            float v1 = src[(size_t)(2 * e + 1) * 4096];
            ph[e] = bsplit_pack_hi(v0, v1, pl[e]);
        }
        uint32_t raw0 = (uint32_t)rr * 2176 + w * 32;
        uint32_t a0 = SWZ(raw0);
        uint32_t a1 = SWZ(raw0 + 16);
        STS128(sb + A_HI + a0, ph[0], ph[1], ph[2], ph[3]);
        STS128(sb + A_HI + a1, ph[4], ph[5], ph[6], ph[7]);
        STS128(sb + A_LO + a0, pl[0], pl[1], pl[2], pl[3]);
        STS128(sb + A_LO + a1, pl[4], pl[5], pl[6], pl[7]);
    }
    __syncthreads();

    int lane = tid & 31;
    int warp = tid >> 5;          // output row within strip (0..15)
    int h = r0 + warp;

    float acc[4][2][4];
    #pragma unroll
    for (int wt = 0; wt < 4; ++wt)
        #pragma unroll
        for (int f = 0; f < 2; ++f)
            #pragma unroll
            for (int e = 0; e < 4; ++e) acc[wt][f][e] = 0.f;

    int arow = lane & 15;
    int khalf = (lane >> 4) * 16;

    #pragma unroll
    for (int kh = 0; kh < 3; ++kh) {
        #pragma unroll
        for (int kw = 0; kw < 3; ++kw) {
            int tap = kh * 3 + kw;
            uint32_t brw = (uint32_t)tap * 512 + arow * 32 + khalf;
            uint32_t baddr = sb + B_SM + SWZ(brw);
            uint32_t bh[4], bl[4];
            LDSM_X4T(bh[0], bh[1], bh[2], bh[3], baddr);
            LDSM_X4T(bl[0], bl[1], bl[2], bl[3], baddr + 4608);

            uint32_t rbase = (uint32_t)(warp + kh) * 2176;
            #pragma unroll
            for (int wt = 0; wt < 4; ++wt) {
                uint32_t araw = rbase + (wt * 16 + arow + kw) * 32 + khalf;
                uint32_t aaddr = sb + SWZ(araw);
                uint32_t ahi[4], alo[4];
                LDSM_X4(ahi[0], ahi[1], ahi[2], ahi[3], aaddr + A_HI);
                LDSM_X4(alo[0], alo[1], alo[2], alo[3], aaddr + A_LO);
                #pragma unroll
                for (int f = 0; f < 2; ++f) {
                    mma16816(acc[wt][f], ahi, bh[2 * f], bh[2 * f + 1]);
                    mma16816(acc[wt][f], ahi, bl[2 * f], bl[2 * f + 1]);
                    mma16816(acc[wt][f], alo, bh[2 * f], bh[2 * f + 1]);
                }
            }
        }
    }

    __syncthreads();  // all A reads done; alias stage buffer onto A region

    // stage: stg[row 16][co 16][w 68] floats = 69632 B (fits in A region)
    float* stg = reinterpret_cast<float*>(smem);
    {
        int wl = lane >> 2;
        int cl = (lane & 3) * 2;
        #pragma unroll
        for (int wt = 0; wt < 4; ++wt)
            #pragma unroll
            for (int f = 0; f < 2; ++f) {
                int w_a = wt * 16 + wl;
                int co = f * 8 + cl;
                float* p0 = &stg[(warp * 16 + co) * 68 + w_a];
                p0[0]   = acc[wt][f][0];
                p0[68]  = acc[wt][f][1];
                p0[8]   = acc[wt][f][2];
                p0[76]  = acc[wt][f][3];
            }
    }
    __syncthreads();

    // coalesced store to g_y[bi][co][h][w]
    float* yb = g_y + (size_t)bi * (16 * 62 * 62);
    for (int idx = tid; idx < 16 * 16 * 62; idx += 512) {
        int w = idx % 62;
        int co = (idx / 62) & 15;
        int row = idx / 992;
        int hg = r0 + row;
        if (hg < 62)
            yb[(co * 62 + hg) * 62 + w] = stg[(row * 16 + co) * 68 + w];
    }
}

// ---------------------------------------------------------------------------
// Kernel 2: mix via mma.sync bf16 split, warp tile m32 x n64.
// Block = 256 pixels x 64 j; grid (16, 16 co, 8 b); 256 threads = 8 warps.
// The second m16 tile reuses B fragments already in registers -> 12 LDSM
// per 48 HMMA per k-step (was 10 per 24).
// ---------------------------------------------------------------------------
static constexpr int PITCH = 144;
static constexpr int SM_AHI  = 0;          // 256*144 = 36864
static constexpr int SM_ALO  = 36864;
static constexpr int SM_BHI  = 73728;      // 64*144 = 9216
static constexpr int SM_BLO  = 82944;
static constexpr int SM_BIAS = 92160;
static constexpr int SM_MIX  = 92416;

__global__ __launch_bounds__(256) void mix_mma_kernel(const float* __restrict__ bias,
                                                      float* __restrict__ out) {
    extern __shared__ __align__(16) char smem[];
    uint32_t sb = smem_u32(smem);
    int tid = threadIdx.x;
    int lane = tid & 31;
    int warp = tid >> 5;
    int co = blockIdx.y;
    int b  = blockIdx.z;
    int p_base = blockIdx.x * 256;

    // ---- B = Wm hi/lo [i][j], row-major, pitch 144B ----
    if (tid < 128) {
        int i = tid & 63;
        int jh = tid >> 6;
        int j0 = jh * 32;
        const float4* src = reinterpret_cast<const float4*>(&g_Wm[i * 64 + j0]);
        uint32_t base = sb + i * PITCH + j0 * 2;
        #pragma unroll
        for (int q = 0; q < 4; ++q) {
            float4 v0 = src[2 * q];
            float4 v1 = src[2 * q + 1];
            uint32_t l0, l1, l2, l3;
            uint32_t h0 = bsplit_pack_hi(v0.x, v0.y, l0);
            uint32_t h1 = bsplit_pack_hi(v0.z, v0.w, l1);
            uint32_t h2 = bsplit_pack_hi(v1.x, v1.y, l2);
            uint32_t h3 = bsplit_pack_hi(v1.z, v1.w, l3);
            STS128(base + SM_BHI + q * 16, h0, h1, h2, h3);
            STS128(base + SM_BLO + q * 16, l0, l1, l2, l3);
        }
    }
    if (tid < 64)
        *reinterpret_cast<float*>(smem + SM_BIAS + tid * 4) = bias[tid];

    // ---- A = y^T [p][i] hi/lo: one thread per pixel row, all 64 i ----
    {
        int p = tid;
        int pg = p_base + p;
        bool pok = pg < 3844;
        const float* ybase = g_y + ((size_t)(b * 64) * 16 + co) * 3844 + pg;
        uint32_t base = sb + p * PITCH;
        #pragma unroll
        for (int s = 0; s < 8; ++s) {
            float v[8];
            #pragma unroll
            for (int e = 0; e < 8; ++e)
                v[e] = pok ? ybase[(size_t)(s * 8 + e) * (16 * 3844)] : 0.f;
            uint32_t l0, l1, l2, l3;
            uint32_t h0 = bsplit_pack_hi(v[0], v[1], l0);
            uint32_t h1 = bsplit_pack_hi(v[2], v[3], l1);
            uint32_t h2 = bsplit_pack_hi(v[4], v[5], l2);
            uint32_t h3 = bsplit_pack_hi(v[6], v[7], l3);
            STS128(base + SM_AHI + s * 16, h0, h1, h2, h3);
            STS128(base + SM_ALO + s * 16, l0, l1, l2, l3);
        }
    }
    __syncthreads();

    float acc[2][8][4];
    #pragma unroll
    for (int mt = 0; mt < 2; ++mt)
        #pragma unroll
        for (int nt = 0; nt < 8; ++nt)
            #pragma unroll
            for (int e = 0; e < 4; ++e) acc[mt][nt][e] = 0.f;

    uint32_t a_row = warp * 32 + (lane & 15);
    uint32_t a_off0 = sb + a_row * PITCH + (lane >> 4) * 16;
    uint32_t a_off1 = a_off0 + 16 * PITCH;
    uint32_t b_kr = (lane & 15);
    uint32_t b_jc = (lane >> 4) * 8;

    #pragma unroll
    for (int k = 0; k < 4; ++k) {
        uint32_t ahi0[4], alo0[4], ahi1[4], alo1[4];
        LDSM_X4(ahi0[0], ahi0[1], ahi0[2], ahi0[3], a_off0 + SM_AHI + k * 32);
        LDSM_X4(alo0[0], alo0[1], alo0[2], alo0[3], a_off0 + SM_ALO + k * 32);
        LDSM_X4(ahi1[0], ahi1[1], ahi1[2], ahi1[3], a_off1 + SM_AHI + k * 32);
        LDSM_X4(alo1[0], alo1[1], alo1[2], alo1[3], a_off1 + SM_ALO + k * 32);

        #pragma unroll
        for (int jp = 0; jp < 4; ++jp) {
            uint32_t baddr = sb + (k * 16 + b_kr) * PITCH + (jp * 16 + b_jc) * 2;
            uint32_t bh[4], bl[4];
            LDSM_X4T(bh[0], bh[1], bh[2], bh[3], baddr + SM_BHI);
            LDSM_X4T(bl[0], bl[1], bl[2], bl[3], baddr + SM_BLO);
            // m-tile 0
            mma16816(acc[0][2 * jp], ahi0, bh[0], bh[1]);
            mma16816(acc[0][2 * jp], ahi0, bl[0], bl[1]);
            mma16816(acc[0][2 * jp], alo0, bh[0], bh[1]);
            mma16816(acc[0][2 * jp + 1], ahi0, bh[2], bh[3]);
            mma16816(acc[0][2 * jp + 1], ahi0, bl[2], bl[3]);
            mma16816(acc[0][2 * jp + 1], alo0, bh[2], bh[3]);
            // m-tile 1 (B fragments reused from registers)
            mma16816(acc[1][2 * jp], ahi1, bh[0], bh[1]);
            mma16816(acc[1][2 * jp], ahi1, bl[0], bl[1]);
            mma16816(acc[1][2 * jp], alo1, bh[0], bh[1]);
            mma16816(acc[1][2 * jp + 1], ahi1, bh[2], bh[3]);
            mma16816(acc[1][2 * jp + 1], ahi1, bl[2], bl[3]);
            mma16816(acc[1][2 * jp + 1], alo1, bh[2], bh[3]);
        }
    }

    size_t rowbase = (size_t)(b * 16 + co) * 3844;
    int jsub = (lane & 3) * 2;

    #pragma unroll
    for (int mt = 0; mt < 2; ++mt) {
        int row0 = warp * 32 + mt * 16 + (lane >> 2);
        int pm0 = p_base + row0;
        int pm1 = pm0 + 8;
        #pragma unroll
        for (int nt = 0; nt < 8; ++nt) {
            int j = nt * 8 + jsub;
            float2 bv = *reinterpret_cast<const float2*>(smem + SM_BIAS + j * 4);
            if (pm0 < 3844)
                *reinterpret_cast<float2*>(&out[(rowbase + pm0) * 64 + j]) =
                    make_float2(acc[mt][nt][0] + bv.x, acc[mt][nt][1] + bv.y);
            if (pm1 < 3844)
                *reinterpret_cast<float2*>(&out[(rowbase + pm1) * 64 + j]) =
                    make_float2(acc[mt][nt][2] + bv.x, acc[mt][nt][3] + bv.y);
        }
    }
}

// ---------------------------------------------------------------------------
extern "C" void kernel_launch(void* const* d_in, const int* in_sizes, int n_in,
                              void* d_out, int out_size) {
    const float* x    = (const float*)d_in[0];
    const float* ker  = (const float*)d_in[1];
    const float* c0   = (const float*)d_in[2];
    const float* c1   = (const float*)d_in[3];
    const float* c2   = (const float*)d_in[4];
    const float* bias = (const float*)d_in[5];
    float* out = (float*)d_out;

    cudaFuncSetAttribute(conv_tc_kernel,
                         cudaFuncAttributeMaxDynamicSharedMemorySize, SM_CONV);
    cudaFuncSetAttribute(mix_mma_kernel,
                         cudaFuncAttributeMaxDynamicSharedMemorySize, SM_MIX);

    conv_tc_kernel<<<2049, 512, SM_CONV>>>(x, ker, c0, c1, c2);
    mix_mma_kernel<<<dim3(16, 16, 8), 256, SM_MIX>>>(bias, out);
}